// round 13
// baseline (speedup 1.0000x reference)
#include <cuda_runtime.h>
#include <cstdint>

// Problem constants
#define BB 8
#define LL 4096
#define DD 768
#define NROWS (BB * LL)        // 32768
#define NB 592                 // 148 SMs x 4 blocks: EVERY SM holds exactly 4
#define NT 256                 // 8 warps
#define BPB 74                 // blocks per batch (592/8)
#define WPB 592                // warps per batch (74*8)
#define CUT 544                // residues < CUT have 7 rows, else 6 (544*7+48*6=4096)

// Scratch (device globals). No cache hints (R2/R3/R8 all failed).
__device__ __align__(16) float g_part[NB * DD];    // per-block column partials (1.8 MB)
__device__ __align__(16) float g_sum[BB * DD];     // full column sums
__device__ float g_sqpart[BB * 6];                 // per-colgroup sum of squares
__device__ unsigned g_arrive = 0;                  // epoch barrier (monotone, replay-safe)

__device__ __forceinline__ void grid_barrier() {
    __syncthreads();
    if (threadIdx.x == 0) {
        __threadfence();
        unsigned old = atomicAdd(&g_arrive, 1u);
        unsigned target = (old / NB + 1u) * NB;
        while ((int)(*(volatile unsigned*)&g_arrive - target) < 0)
            __nanosleep(32);
    }
    __syncthreads();
}

__global__ __launch_bounds__(NT, 4) void fused_kernel(const float* __restrict__ x,
                                                      const float* __restrict__ alpha,
                                                      float* __restrict__ out) {
    __shared__ float4 s_acc[8][DD / 4];   // 24 KB: per-warp column partials (phase 1)
    __shared__ float red[NT];             // phase 2 reduce

    const int tid  = threadIdx.x;
    const int bid  = blockIdx.x;
    const int warp = tid >> 5;
    const int lane = tid & 31;

    const int b  = bid / BPB;                    // batch, fixed per block
    const int wb = (bid % BPB) * 8 + warp;       // warp-in-batch, 0..591
    const int cnt = (wb < CUT) ? 7 : 6;          // rows this warp owns (both phases)
    const float* xb = x + ((size_t)b << 12) * DD;

    // ---- Phase 1: column sums. Warp handles rows l = wb + k*592 (ascending).
    // ~1.2% imbalance; all batches swept concurrently, so phase 1 ends with
    // the HIGH-l band of every batch most recently touched in L2.
    {
        float4 acc[6];
#pragma unroll
        for (int i = 0; i < 6; i++) acc[i] = make_float4(0.f, 0.f, 0.f, 0.f);
        for (int k = 0; k < cnt; k++) {
            const int l = wb + k * WPB;
            const float4* xp = reinterpret_cast<const float4*>(xb + (size_t)l * DD) + lane;
#pragma unroll
            for (int i = 0; i < 6; i++) {
                float4 v = xp[i * 32];
                acc[i].x += v.x; acc[i].y += v.y; acc[i].z += v.z; acc[i].w += v.w;
            }
        }
#pragma unroll
        for (int i = 0; i < 6; i++) s_acc[warp][lane + i * 32] = acc[i];
        __syncthreads();

        // 256 threads reduce 8 warp-partials x 768 cols (3 cols/thread)
        const float* sa = reinterpret_cast<const float*>(s_acc);
#pragma unroll
        for (int k = 0; k < 3; k++) {
            const int col = tid + k * NT;
            float s = ((sa[0 * DD + col] + sa[1 * DD + col])
                     + (sa[2 * DD + col] + sa[3 * DD + col]))
                    + ((sa[4 * DD + col] + sa[5 * DD + col])
                     + (sa[6 * DD + col] + sa[7 * DD + col]));
            g_part[(size_t)bid * DD + col] = s;
        }
    }

    grid_barrier();

    // ---- Phase 2: 48 blocks (8 batches x 6 col-groups of 128). Reduce the 74
    // block-partials of each batch; also per-group sum of squares (~1.8 MB, L2).
    if (bid < 48) {
        const int pb = bid / 6;
        const int g  = bid % 6;
        if (tid < 128) {
            const int col = g * 128 + tid;
            const float* p = g_part + (size_t)pb * BPB * DD + col;
            float a0 = 0.f, a1 = 0.f;
#pragma unroll 2
            for (int k = 0; k < BPB - 1; k += 2) {
                a0 += p[(size_t)(k + 0) * DD];
                a1 += p[(size_t)(k + 1) * DD];
            }
            const float s = a0 + a1 + p[(size_t)(BPB - 1) * DD];
            g_sum[pb * DD + col] = s;
            red[tid] = s * s;
        }
        __syncthreads();
        if (tid < 64) red[tid] += red[tid + 64];
        __syncthreads();
        if (tid < 32) {
            float v = red[tid] + red[tid + 32];
#pragma unroll
            for (int off = 16; off > 0; off >>= 1)
                v += __shfl_xor_sync(0xFFFFFFFFu, v, off);
            if (tid == 0) g_sqpart[pb * 6 + g] = v;
        }
    }

    grid_barrier();

    // ---- Phase 3: finalize. Same residue classes, l DESCENDING, all batches
    // concurrently — the read frontier consumes exactly the high-l band phase 1
    // left hot, then tracks down ahead of the write-eviction wave. No syncs.
    {
        const float sq = (g_sqpart[b * 6 + 0] + g_sqpart[b * 6 + 1])
                       + (g_sqpart[b * 6 + 2] + g_sqpart[b * 6 + 3])
                       + (g_sqpart[b * 6 + 4] + g_sqpart[b * 6 + 5]);
        const double denom = (double)DD * (double)DD
                           * (double)LL * (double)LL * (double)LL * (double)LL;
        const float coef = (float)((double)sq / denom);
        const float4* mp = reinterpret_cast<const float4*>(g_sum + b * DD);
        float4 m[6];
#pragma unroll
        for (int i = 0; i < 6; i++) m[i] = mp[lane + i * 32];

        float* ob = out + ((size_t)b << 12) * DD;
        const int lmax = wb + (cnt - 1) * WPB;

        for (int k = 0; k < cnt; k++) {
            const int l = lmax - k * WPB;        // descending
            const float4* xp = reinterpret_cast<const float4*>(xb + (size_t)l * DD) + lane;
            float4 v[6];
            float dot = 0.f;
#pragma unroll
            for (int i = 0; i < 6; i++) {
                v[i] = xp[i * 32];
                dot += v[i].x * m[i].x + v[i].y * m[i].y
                     + v[i].z * m[i].z + v[i].w * m[i].w;
            }
#pragma unroll
            for (int off = 16; off > 0; off >>= 1)
                dot += __shfl_xor_sync(0xFFFFFFFFu, dot, off);

            const float y2 = dot * coef;
            const float a  = alpha[l];

            float4* op = reinterpret_cast<float4*>(ob + (size_t)l * DD) + lane;
#pragma unroll
            for (int i = 0; i < 6; i++) {
                float4 o;
                o.x = a + y2 * v[i].x;
                o.y = a + y2 * v[i].y;
                o.z = a + y2 * v[i].z;
                o.w = a + y2 * v[i].w;
                op[i * 32] = o;
            }
        }
    }
}

extern "C" void kernel_launch(void* const* d_in, const int* in_sizes, int n_in,
                              void* d_out, int out_size) {
    const float* x     = (const float*)d_in[0];   // [8, 4096, 768] f32
    const float* alpha = (const float*)d_in[1];   // [4096, 1] f32
    float* out = (float*)d_out;                   // [8, 4096, 768] f32

    fused_kernel<<<NB, NT>>>(x, alpha, out);
}

// round 14
// speedup vs baseline: 1.0381x; 1.0381x over previous
#include <cuda_runtime.h>
#include <cstdint>

// Problem constants
#define BB 8
#define LL 4096
#define DD 768
#define NROWS (BB * LL)        // 32768
#define NB 592                 // 148 SMs x 4 blocks: EVERY SM holds exactly 4
#define NT 256                 // 8 warps
#define BPB 74                 // blocks per batch (592/8)
#define WPB 592                // warps per batch

// Scratch (device globals). No cache hints (R2/R3/R8 all failed).
__device__ __align__(16) float g_part[NB * DD];    // per-block column partials (1.8 MB)
__device__ __align__(16) float g_sum[BB * DD];     // full column sums
__device__ float g_sqpart[BB * 6];                 // per-colgroup sum of squares
__device__ unsigned g_arrive = 0;                  // epoch barrier (monotone, replay-safe)

__device__ __forceinline__ void grid_barrier() {
    __syncthreads();
    if (threadIdx.x == 0) {
        __threadfence();
        unsigned old = atomicAdd(&g_arrive, 1u);
        unsigned target = (old / NB + 1u) * NB;
        while ((int)(*(volatile unsigned*)&g_arrive - target) < 0)
            __nanosleep(32);
    }
    __syncthreads();
}

__global__ __launch_bounds__(NT, 4) void fused_kernel(const float* __restrict__ x,
                                                      const float* __restrict__ alpha,
                                                      float* __restrict__ out) {
    __shared__ float4 s_acc[8][DD / 4];   // 24 KB: per-warp column partials (phase 1)
    __shared__ float red[NT];             // phase 2 reduce

    const int tid  = threadIdx.x;
    const int bid  = blockIdx.x;
    const int warp = tid >> 5;
    const int lane = tid & 31;

    const int b  = bid / BPB;                    // batch, fixed per block
    const int w  = (bid % BPB) * 8 + warp;       // warp-in-batch, 0..591
    // Contiguous fractional window: rows [r0, r0+cnt) of batch b (cnt = 6 or 7)
    const int r0  = (w * LL) / WPB;
    const int cnt = ((w + 1) * LL) / WPB - r0;
    const float* xb = x + ((size_t)b << 12) * DD;

    // ---- Phase 1: column sums over the warp's consecutive rows (ascending).
    // Consecutive 18-21 KB run per warp = same locality/MLP as R11's layout.
    {
        float4 acc[6];
#pragma unroll
        for (int i = 0; i < 6; i++) acc[i] = make_float4(0.f, 0.f, 0.f, 0.f);
        const float4* xp = reinterpret_cast<const float4*>(xb + (size_t)r0 * DD) + lane;
        for (int k = 0; k < cnt; k++) {
#pragma unroll
            for (int i = 0; i < 6; i++) {
                float4 v = xp[(size_t)k * (DD / 4) + i * 32];
                acc[i].x += v.x; acc[i].y += v.y; acc[i].z += v.z; acc[i].w += v.w;
            }
        }
#pragma unroll
        for (int i = 0; i < 6; i++) s_acc[warp][lane + i * 32] = acc[i];
        __syncthreads();

        // 256 threads reduce 8 warp-partials x 768 cols (3 cols/thread)
        const float* sa = reinterpret_cast<const float*>(s_acc);
#pragma unroll
        for (int k = 0; k < 3; k++) {
            const int col = tid + k * NT;
            float s = ((sa[0 * DD + col] + sa[1 * DD + col])
                     + (sa[2 * DD + col] + sa[3 * DD + col]))
                    + ((sa[4 * DD + col] + sa[5 * DD + col])
                     + (sa[6 * DD + col] + sa[7 * DD + col]));
            g_part[(size_t)bid * DD + col] = s;
        }
    }

    grid_barrier();

    // ---- Phase 2: 48 blocks (8 batches x 6 col-groups of 128). Reduce the 74
    // block-partials of each batch; per-group sum of squares (~1.8 MB, L2).
    if (bid < 48) {
        const int pb = bid / 6;
        const int g  = bid % 6;
        if (tid < 128) {
            const int col = g * 128 + tid;
            const float* p = g_part + (size_t)pb * BPB * DD + col;
            float a0 = 0.f, a1 = 0.f;
#pragma unroll 2
            for (int k = 0; k < BPB - 1; k += 2) {
                a0 += p[(size_t)(k + 0) * DD];
                a1 += p[(size_t)(k + 1) * DD];
            }
            const float s = a0 + a1 + p[(size_t)(BPB - 1) * DD];
            g_sum[pb * DD + col] = s;
            red[tid] = s * s;
        }
        __syncthreads();
        if (tid < 64) red[tid] += red[tid + 64];
        __syncthreads();
        if (tid < 32) {
            float v = red[tid] + red[tid + 32];
#pragma unroll
            for (int off = 16; off > 0; off >>= 1)
                v += __shfl_xor_sync(0xFFFFFFFFu, v, off);
            if (tid == 0) g_sqpart[pb * 6 + g] = v;
        }
    }

    grid_barrier();

    // ---- Phase 3: finalize over the SAME windows, rows DESCENDING. All warps
    // sit at the same fractional position -> coherent global frontier; the
    // second x read stays mostly L2-resident (~75-85 MB saved; R6/R9-R11 data).
    // No block syncs; sum_b cached in registers per warp.
    {
        const float sq = (g_sqpart[b * 6 + 0] + g_sqpart[b * 6 + 1])
                       + (g_sqpart[b * 6 + 2] + g_sqpart[b * 6 + 3])
                       + (g_sqpart[b * 6 + 4] + g_sqpart[b * 6 + 5]);
        const double denom = (double)DD * (double)DD
                           * (double)LL * (double)LL * (double)LL * (double)LL;
        const float coef = (float)((double)sq / denom);
        const float4* mp = reinterpret_cast<const float4*>(g_sum + b * DD);
        float4 m[6];
#pragma unroll
        for (int i = 0; i < 6; i++) m[i] = mp[lane + i * 32];

        float* ob = out + ((size_t)b << 12) * DD;

        for (int k = cnt - 1; k >= 0; k--) {
            const int l = r0 + k;                 // descending within window
            const float4* xp = reinterpret_cast<const float4*>(xb + (size_t)l * DD) + lane;
            float4 v[6];
            float dot = 0.f;
#pragma unroll
            for (int i = 0; i < 6; i++) {
                v[i] = xp[i * 32];
                dot += v[i].x * m[i].x + v[i].y * m[i].y
                     + v[i].z * m[i].z + v[i].w * m[i].w;
            }
#pragma unroll
            for (int off = 16; off > 0; off >>= 1)
                dot += __shfl_xor_sync(0xFFFFFFFFu, dot, off);

            const float y2 = dot * coef;
            const float a  = alpha[l];

            float4* op = reinterpret_cast<float4*>(ob + (size_t)l * DD) + lane;
#pragma unroll
            for (int i = 0; i < 6; i++) {
                float4 o;
                o.x = a + y2 * v[i].x;
                o.y = a + y2 * v[i].y;
                o.z = a + y2 * v[i].z;
                o.w = a + y2 * v[i].w;
                op[i * 32] = o;
            }
        }
    }
}

extern "C" void kernel_launch(void* const* d_in, const int* in_sizes, int n_in,
                              void* d_out, int out_size) {
    const float* x     = (const float*)d_in[0];   // [8, 4096, 768] f32
    const float* alpha = (const float*)d_in[1];   // [4096, 1] f32
    float* out = (float*)d_out;                   // [8, 4096, 768] f32

    fused_kernel<<<NB, NT>>>(x, alpha, out);
}

// round 15
// speedup vs baseline: 1.0576x; 1.0188x over previous
#include <cuda_runtime.h>
#include <cstdint>

// Problem constants
#define BB 8
#define LL 4096
#define DD 768
#define NROWS (BB * LL)        // 32768
#define NB 512                 // blocks (148*4 = 592 co-resident slots >= 512)
#define NT 256                 // 8 warps
#define RPW 8                  // rows per warp (phase 1): 512*8*8 = 32768 exact

// Scratch (device globals). No cache hints (R2/R3/R8 all failed).
__device__ __align__(16) float g_part[NB * DD];    // per-block column partials (1.5 MB)
__device__ __align__(16) float g_sum[BB * DD];     // full column sums
__device__ float g_sqpart[BB * 3];                 // per-colgroup sum of squares
__device__ unsigned g_arrive = 0;                  // epoch barrier (monotone, replay-safe)

__device__ __forceinline__ void grid_barrier() {
    __syncthreads();
    if (threadIdx.x == 0) {
        __threadfence();
        unsigned old = atomicAdd(&g_arrive, 1u);
        unsigned target = (old / NB + 1u) * NB;
        while ((int)(*(volatile unsigned*)&g_arrive - target) < 0)
            __nanosleep(32);
    }
    __syncthreads();
}

__global__ __launch_bounds__(NT, 4) void fused_kernel(const float* __restrict__ x,
                                                      const float* __restrict__ alpha,
                                                      float* __restrict__ out) {
    // 24 KB buffer: phase 1 = per-warp column partials; phase 3 = all 8 sum_b rows.
    __shared__ float4 s_buf[8][DD / 4];
    __shared__ float red[NT];             // phase 2 reduce
    __shared__ float s_coef[BB];          // phase 3: per-batch coefficient

    const int tid  = threadIdx.x;
    const int bid  = blockIdx.x;
    const int warp = tid >> 5;
    const int lane = tid & 31;

    // ---- Phase 1: column sums. One warp = exactly 8 consecutive rows; one
    // block = 64 rows (one batch spans 64 consecutive blocks). No atomics.
    {
        const size_t rowbase = (size_t)bid * 64 + warp * RPW;
        const float4* xp = reinterpret_cast<const float4*>(x) + rowbase * (DD / 4) + lane;

        float4 acc[6];
#pragma unroll
        for (int i = 0; i < 6; i++) acc[i] = make_float4(0.f, 0.f, 0.f, 0.f);
#pragma unroll
        for (int r = 0; r < RPW; r++) {
#pragma unroll
            for (int i = 0; i < 6; i++) {
                float4 v = xp[(size_t)r * (DD / 4) + i * 32];
                acc[i].x += v.x; acc[i].y += v.y; acc[i].z += v.z; acc[i].w += v.w;
            }
        }
#pragma unroll
        for (int i = 0; i < 6; i++) s_buf[warp][lane + i * 32] = acc[i];
        __syncthreads();

        // 256 threads reduce 8 warp-partials x 768 cols (3 cols/thread)
        const float* sa = reinterpret_cast<const float*>(s_buf);
#pragma unroll
        for (int k = 0; k < 3; k++) {
            const int col = tid + k * NT;
            float s = ((sa[0 * DD + col] + sa[1 * DD + col])
                     + (sa[2 * DD + col] + sa[3 * DD + col]))
                    + ((sa[4 * DD + col] + sa[5 * DD + col])
                     + (sa[6 * DD + col] + sa[7 * DD + col]));
            g_part[(size_t)bid * DD + col] = s;
        }
    }

    grid_barrier();

    // ---- Phase 2: 24 blocks (8 batches x 3 col-groups of 256). Reduce the 64
    // block-partials of each batch; per-group sum of squares (~1.5 MB, L2). ----
    if (bid < 24) {
        const int b = bid / 3;
        const int g = bid % 3;
        const int col = g * 256 + tid;

        const float* p = g_part + (size_t)b * 64 * DD + col;
        float a0 = 0.f, a1 = 0.f, a2 = 0.f, a3 = 0.f;
#pragma unroll
        for (int k = 0; k < 64; k += 4) {
            a0 += p[(size_t)(k + 0) * DD];
            a1 += p[(size_t)(k + 1) * DD];
            a2 += p[(size_t)(k + 2) * DD];
            a3 += p[(size_t)(k + 3) * DD];
        }
        const float s = (a0 + a1) + (a2 + a3);
        g_sum[b * DD + col] = s;

        red[tid] = s * s;
        __syncthreads();
        if (tid < 128) red[tid] += red[tid + 128];
        __syncthreads();
        if (tid < 64) red[tid] += red[tid + 64];
        __syncthreads();
        if (tid < 32) {
            float v = red[tid] + red[tid + 32];
#pragma unroll
            for (int off = 16; off > 0; off >>= 1)
                v += __shfl_xor_sync(0xFFFFFFFFu, v, off);
            if (tid == 0) g_sqpart[b * 3 + g] = v;
        }
    }

    grid_barrier();

    // ---- Phase 3: finalize, batches DESCENDING, SYNC-FREE loop.
    // Preload ALL 8 sum_b rows (24 KB, reusing s_buf) + 8 coefs, ONE sync,
    // then 8 fully independent per-warp iterations. At iteration j all 4096
    // warps process batch 7-j — the coherent 12 MB frontier that keeps the
    // second x read in L2 (~75-85 MB saved; measured R6, R9-R11).
    {
        // 256 threads load 8 x 192 float4 = 6 float4 each
#pragma unroll
        for (int k = 0; k < 6; k++) {
            const int idx = tid + k * NT;               // 0..1535
            reinterpret_cast<float4*>(s_buf)[idx] =
                reinterpret_cast<const float4*>(g_sum)[idx];
        }
        if (tid < BB) {
            const float sq = g_sqpart[tid * 3 + 0] + g_sqpart[tid * 3 + 1]
                           + g_sqpart[tid * 3 + 2];
            const double denom = (double)DD * (double)DD
                               * (double)LL * (double)LL * (double)LL * (double)LL;
            s_coef[tid] = (float)((double)sq / denom);
        }
        __syncthreads();   // the only phase-3 sync

        const int wg = bid * 8 + warp;          // 0..4095
        const int l  = 4095 - wg;
        const float a = alpha[l];

#pragma unroll 1
        for (int j = 0; j < 8; j++) {
            const int b = 7 - j;
            const float coef = s_coef[b];

            const int row = (b << 12) | l;
            const float4* xp = reinterpret_cast<const float4*>(x + (size_t)row * DD);
            float4 v[6];
            float dot = 0.f;
#pragma unroll
            for (int i = 0; i < 6; i++) {
                v[i] = xp[lane + i * 32];
                float4 m = s_buf[b][lane + i * 32];
                dot += v[i].x * m.x + v[i].y * m.y + v[i].z * m.z + v[i].w * m.w;
            }
#pragma unroll
            for (int off = 16; off > 0; off >>= 1)
                dot += __shfl_xor_sync(0xFFFFFFFFu, dot, off);

            const float y2 = dot * coef;

            float4* op = reinterpret_cast<float4*>(out + (size_t)row * DD);
#pragma unroll
            for (int i = 0; i < 6; i++) {
                float4 o;
                o.x = a + y2 * v[i].x;
                o.y = a + y2 * v[i].y;
                o.z = a + y2 * v[i].z;
                o.w = a + y2 * v[i].w;
                op[lane + i * 32] = o;
            }
        }
    }
}

extern "C" void kernel_launch(void* const* d_in, const int* in_sizes, int n_in,
                              void* d_out, int out_size) {
    const float* x     = (const float*)d_in[0];   // [8, 4096, 768] f32
    const float* alpha = (const float*)d_in[1];   // [4096, 1] f32
    float* out = (float*)d_out;                   // [8, 4096, 768] f32

    fused_kernel<<<NB, NT>>>(x, alpha, out);
}